// round 5
// baseline (speedup 1.0000x reference)
#include <cuda_runtime.h>
#include <cuda_bf16.h>

// Problem constants (reference: N=100000, E=1000000, D=64)
#define MAXN 100000
#define MAXE 1000000
#define DIMF 64

// Scratch (device globals; no allocation allowed)
__device__ float g_agg[MAXN * DIMF];
__device__ float g_h1[MAXN * DIMF];
__device__ float g_h2[MAXN * DIMF];
__device__ int   g_cnt[MAXN];
__device__ int   g_rowptr[MAXN + 1];
__device__ int   g_cursor[MAXN];
__device__ int2  g_edata[MAXE];          // {src, float_bits(w)} sorted by dst
__device__ int   g_bsum[512];

// ---------------------------------------------------------------------------
// CSR build: histogram -> exclusive scan -> fill
// ---------------------------------------------------------------------------
__global__ void zero_cnt_kernel(int* __restrict__ cnt, int N) {
    int i = blockIdx.x * blockDim.x + threadIdx.x;
    if (i < N) cnt[i] = 0;
}

__global__ void hist_kernel(const int* __restrict__ dst, int* __restrict__ cnt, int E) {
    int e = blockIdx.x * blockDim.x + threadIdx.x;
    if (e < E) atomicAdd(&cnt[dst[e]], 1);
}

// Per-block sums of cnt (256 per block)
__global__ void scan_partial_kernel(const int* __restrict__ cnt, int* __restrict__ bsum, int N) {
    __shared__ int sm[256];
    int i = blockIdx.x * 256 + threadIdx.x;
    sm[threadIdx.x] = (i < N) ? cnt[i] : 0;
    __syncthreads();
    for (int s = 128; s > 0; s >>= 1) {
        if (threadIdx.x < s) sm[threadIdx.x] += sm[threadIdx.x + s];
        __syncthreads();
    }
    if (threadIdx.x == 0) bsum[blockIdx.x] = sm[0];
}

// Single-block exclusive scan of bsum (up to 512 entries)
__global__ void scan_top_kernel(int* __restrict__ bsum, int NB) {
    __shared__ int sm[512];
    int t = threadIdx.x;
    int v = (t < NB) ? bsum[t] : 0;
    sm[t] = v;
    __syncthreads();
    for (int s = 1; s < 512; s <<= 1) {
        int add = (t >= s) ? sm[t - s] : 0;
        __syncthreads();
        sm[t] += add;
        __syncthreads();
    }
    if (t < NB) bsum[t] = sm[t] - v;   // exclusive
}

// Local exclusive scan + global offset -> rowptr & cursor; rowptr[N] written too
__global__ void scan_final_kernel(const int* __restrict__ cnt,
                                  const int* __restrict__ bsum,
                                  int* __restrict__ rowptr,
                                  int* __restrict__ cursor, int N) {
    __shared__ int sm[256];
    int t = threadIdx.x;
    int i = blockIdx.x * 256 + t;
    int v = (i < N) ? cnt[i] : 0;
    sm[t] = v;
    __syncthreads();
    for (int s = 1; s < 256; s <<= 1) {
        int add = (t >= s) ? sm[t - s] : 0;
        __syncthreads();
        sm[t] += add;
        __syncthreads();
    }
    int val = bsum[blockIdx.x] + sm[t] - v;   // exclusive prefix
    if (i < N) {
        rowptr[i] = val;
        cursor[i] = val;
    } else if (i == N) {
        rowptr[N] = val;                      // == E
    }
}

__global__ void fill_kernel(const int* __restrict__ src, const int* __restrict__ dst,
                            const float* __restrict__ ew,
                            int* __restrict__ cursor, int2* __restrict__ edata, int E) {
    int e = blockIdx.x * blockDim.x + threadIdx.x;
    if (e >= E) return;
    int d = dst[e];
    int p = atomicAdd(&cursor[d], 1);
    edata[p] = make_int2(src[e], __float_as_int(ew[e]));
}

// ---------------------------------------------------------------------------
// Gather-aggregate: agg[n] = x[n] + sum_{e in csr(n)} x[src_e] * w_e
// 16 lanes per node (one float4 chunk each); no atomics.
// ---------------------------------------------------------------------------
__global__ void gather_kernel(const float4* __restrict__ x4,
                              const int* __restrict__ rowptr,
                              const int2* __restrict__ edata,
                              float4* __restrict__ agg, int N) {
    int idx = blockIdx.x * blockDim.x + threadIdx.x;
    int n = idx >> 4;
    if (n >= N) return;
    int c = idx & 15;
    int beg = __ldg(rowptr + n);
    int end = __ldg(rowptr + n + 1);
    float4 acc = x4[(size_t)n * 16 + c];    // GIN identity term
    for (int e = beg; e < end; e++) {
        int2 ed = __ldg(edata + e);
        float w = __int_as_float(ed.y);
        float4 v = x4[(size_t)ed.x * 16 + c];
        acc.x += v.x * w; acc.y += v.y * w;
        acc.z += v.z * w; acc.w += v.w * w;
    }
    agg[(size_t)n * 16 + c] = acc;
}

// ---------------------------------------------------------------------------
// Fused MLP: out = [relu]( relu(agg @ W1 + b1) @ W2 + b2 )   (unchanged R4)
// ---------------------------------------------------------------------------
template<int H, bool RELU_OUT>
__global__ void __launch_bounds__(256, 2) mlp_kernel(
        const float4* __restrict__ agg4,
        const float* __restrict__ w1, const float* __restrict__ b1,
        const float* __restrict__ w2, const float* __restrict__ b2,
        float4* __restrict__ out4, int N) {
    constexpr int TR  = 64;
    constexpr int INS = 65;
    constexpr int NP  = H / 64;

    extern __shared__ float sm[];
    float4* in_v = (float4*)sm;               // 16 * INS float4
    float*  w1t  = sm + 16 * INS * 4;         // H * 64
    float4* hid4 = (float4*)sm;               // reuses in_v+w1t region
    float*  w2t  = w1t + H * 64;              // 64 * H
    float*  b1s  = w2t + 64 * H;              // H
    float*  b2s  = b1s + H;                   // 64

    int tid  = threadIdx.x;
    int row0 = blockIdx.x * TR;
    int nrows = N - row0; if (nrows > TR) nrows = TR;

    for (int i = tid; i < 64 * H; i += 256) {
        int k = i / H, c = i % H;
        w1t[c * 64 + k] = w1[i];
    }
    for (int i = tid; i < H * 64; i += 256) {
        int h = i / 64, c = i % 64;
        w2t[c * H + h] = w2[i];
    }
    if (tid < H)  b1s[tid] = b1[tid];
    if (tid < 64) b2s[tid] = b2[tid];

    for (int i = tid; i < TR * 16; i += 256) {
        int r = i >> 4, k4 = i & 15;
        float4 v = make_float4(0.f, 0.f, 0.f, 0.f);
        if (r < nrows) v = agg4[(size_t)(row0 + r) * 16 + k4];
        in_v[k4 * INS + r] = v;
    }
    __syncthreads();

    const int rg = tid & 15;
    const int cg = tid >> 4;

    float acc1[NP][4][4];
    #pragma unroll
    for (int p = 0; p < NP; p++) {
        int c0 = (p * 16 + cg) * 4;
        #pragma unroll
        for (int j = 0; j < 4; j++) {
            acc1[p][j][0] = b1s[c0];     acc1[p][j][1] = b1s[c0 + 1];
            acc1[p][j][2] = b1s[c0 + 2]; acc1[p][j][3] = b1s[c0 + 3];
        }
    }
    #pragma unroll
    for (int k4 = 0; k4 < 16; ++k4) {
        float4 iv[4];
        #pragma unroll
        for (int j = 0; j < 4; j++) iv[j] = in_v[k4 * INS + rg + 16 * j];
        #pragma unroll
        for (int p = 0; p < NP; p++) {
            int c0 = (p * 16 + cg) * 4;
            float4 wv0 = *(const float4*)(w1t + (c0 + 0) * 64 + k4 * 4);
            float4 wv1 = *(const float4*)(w1t + (c0 + 1) * 64 + k4 * 4);
            float4 wv2 = *(const float4*)(w1t + (c0 + 2) * 64 + k4 * 4);
            float4 wv3 = *(const float4*)(w1t + (c0 + 3) * 64 + k4 * 4);
            #pragma unroll
            for (int j = 0; j < 4; j++) {
                acc1[p][j][0] += iv[j].x * wv0.x + iv[j].y * wv0.y + iv[j].z * wv0.z + iv[j].w * wv0.w;
                acc1[p][j][1] += iv[j].x * wv1.x + iv[j].y * wv1.y + iv[j].z * wv1.z + iv[j].w * wv1.w;
                acc1[p][j][2] += iv[j].x * wv2.x + iv[j].y * wv2.y + iv[j].z * wv2.z + iv[j].w * wv2.w;
                acc1[p][j][3] += iv[j].x * wv3.x + iv[j].y * wv3.y + iv[j].z * wv3.z + iv[j].w * wv3.w;
            }
        }
    }
    __syncthreads();

    #pragma unroll
    for (int p = 0; p < NP; p++) {
        #pragma unroll
        for (int j = 0; j < 4; j++) {
            hid4[(p * 16 + cg) * 64 + rg + 16 * j] = make_float4(
                fmaxf(acc1[p][j][0], 0.f), fmaxf(acc1[p][j][1], 0.f),
                fmaxf(acc1[p][j][2], 0.f), fmaxf(acc1[p][j][3], 0.f));
        }
    }
    __syncthreads();

    {
        int c0 = cg * 4;
        float acc[4][4];
        #pragma unroll
        for (int j = 0; j < 4; j++) {
            acc[j][0] = b2s[c0];     acc[j][1] = b2s[c0 + 1];
            acc[j][2] = b2s[c0 + 2]; acc[j][3] = b2s[c0 + 3];
        }
        #pragma unroll
        for (int h4 = 0; h4 < H / 4; ++h4) {
            float4 hv[4];
            #pragma unroll
            for (int j = 0; j < 4; j++) hv[j] = hid4[h4 * 64 + rg + 16 * j];
            float4 wv0 = *(const float4*)(w2t + (c0 + 0) * H + h4 * 4);
            float4 wv1 = *(const float4*)(w2t + (c0 + 1) * H + h4 * 4);
            float4 wv2 = *(const float4*)(w2t + (c0 + 2) * H + h4 * 4);
            float4 wv3 = *(const float4*)(w2t + (c0 + 3) * H + h4 * 4);
            #pragma unroll
            for (int j = 0; j < 4; j++) {
                acc[j][0] += hv[j].x * wv0.x + hv[j].y * wv0.y + hv[j].z * wv0.z + hv[j].w * wv0.w;
                acc[j][1] += hv[j].x * wv1.x + hv[j].y * wv1.y + hv[j].z * wv1.z + hv[j].w * wv1.w;
                acc[j][2] += hv[j].x * wv2.x + hv[j].y * wv2.y + hv[j].z * wv2.z + hv[j].w * wv2.w;
                acc[j][3] += hv[j].x * wv3.x + hv[j].y * wv3.y + hv[j].z * wv3.z + hv[j].w * wv3.w;
            }
        }
        #pragma unroll
        for (int j = 0; j < 4; j++) {
            int r = rg + 16 * j;
            if (r < nrows) {
                float4 v;
                if (RELU_OUT) {
                    v = make_float4(fmaxf(acc[j][0], 0.f), fmaxf(acc[j][1], 0.f),
                                    fmaxf(acc[j][2], 0.f), fmaxf(acc[j][3], 0.f));
                } else {
                    v = make_float4(acc[j][0], acc[j][1], acc[j][2], acc[j][3]);
                }
                out4[(size_t)(row0 + r) * 16 + cg] = v;
            }
        }
    }
}

// ---------------------------------------------------------------------------
// Launch
// ---------------------------------------------------------------------------
static inline size_t mlp_smem(int H) {
    size_t region0 = 16 * 65 * 4 + (size_t)H * 64;  // in_v + w1t (>= hid)
    return (region0 + 64 * H + H + 64) * sizeof(float);
}

extern "C" void kernel_launch(void* const* d_in, const int* in_sizes, int n_in,
                              void* d_out, int out_size) {
    const float* x   = (const float*)d_in[0];
    const int*   ei  = (const int*)d_in[1];
    const float* ew  = (const float*)d_in[2];
    const float* w11 = (const float*)d_in[3];
    const float* b11 = (const float*)d_in[4];
    const float* w12 = (const float*)d_in[5];
    const float* b12 = (const float*)d_in[6];
    const float* w21 = (const float*)d_in[7];
    const float* b21 = (const float*)d_in[8];
    const float* w22 = (const float*)d_in[9];
    const float* b22 = (const float*)d_in[10];
    const float* w31 = (const float*)d_in[11];
    const float* b31 = (const float*)d_in[12];
    const float* w32 = (const float*)d_in[13];
    const float* b32 = (const float*)d_in[14];
    float* out = (float*)d_out;

    int N = in_sizes[0] / DIMF;
    int E = in_sizes[1] / 2;
    const int* src = ei;
    const int* dst = ei + E;

    float *agg, *h1, *h2;
    int *cnt, *rowptr, *cursor, *bsum;
    int2 *edata;
    cudaGetSymbolAddress((void**)&agg, g_agg);
    cudaGetSymbolAddress((void**)&h1, g_h1);
    cudaGetSymbolAddress((void**)&h2, g_h2);
    cudaGetSymbolAddress((void**)&cnt, g_cnt);
    cudaGetSymbolAddress((void**)&rowptr, g_rowptr);
    cudaGetSymbolAddress((void**)&cursor, g_cursor);
    cudaGetSymbolAddress((void**)&bsum, g_bsum);
    cudaGetSymbolAddress((void**)&edata, g_edata);

    size_t sm64  = mlp_smem(64);
    size_t sm128 = mlp_smem(128);
    cudaFuncSetAttribute(mlp_kernel<64, true>,  cudaFuncAttributeMaxDynamicSharedMemorySize, (int)sm64);
    cudaFuncSetAttribute(mlp_kernel<128, true>, cudaFuncAttributeMaxDynamicSharedMemorySize, (int)sm128);
    cudaFuncSetAttribute(mlp_kernel<64, false>, cudaFuncAttributeMaxDynamicSharedMemorySize, (int)sm64);

    int NB = (N + 255) / 256;                // scan blocks (<=512 required)
    int eb = (E + 255) / 256;
    int gb = (N * 16 + 255) / 256;
    int mb = (N + 63) / 64;

    // --- CSR build (by destination) ---
    zero_cnt_kernel<<<NB, 256>>>(cnt, N);
    hist_kernel<<<eb, 256>>>(dst, cnt, E);
    scan_partial_kernel<<<NB, 256>>>(cnt, bsum, N);
    scan_top_kernel<<<1, 512>>>(bsum, NB);
    scan_final_kernel<<<NB + 1, 256>>>(cnt, bsum, rowptr, cursor, N);
    fill_kernel<<<eb, 256>>>(src, dst, ew, cursor, edata, E);

    // --- Layer 1: 64 -> 64 -> 64, relu ---
    gather_kernel<<<gb, 256>>>((const float4*)x, rowptr, edata, (float4*)agg, N);
    mlp_kernel<64, true><<<mb, 256, sm64>>>((const float4*)agg, w11, b11, w12, b12, (float4*)h1, N);

    // --- Layer 2: 64 -> 128 -> 64, relu ---
    gather_kernel<<<gb, 256>>>((const float4*)h1, rowptr, edata, (float4*)agg, N);
    mlp_kernel<128, true><<<mb, 256, sm128>>>((const float4*)agg, w21, b21, w22, b22, (float4*)h2, N);

    // --- Layer 3: 64 -> 64 -> 64, no relu ---
    gather_kernel<<<gb, 256>>>((const float4*)h2, rowptr, edata, (float4*)agg, N);
    mlp_kernel<64, false><<<mb, 256, sm64>>>((const float4*)agg, w31, b31, w32, b32, (float4*)out, N);
}

// round 6
// speedup vs baseline: 1.5488x; 1.5488x over previous
#include <cuda_runtime.h>
#include <cuda_bf16.h>

// Problem constants (reference: N=100000, E=1000000, D=64)
#define MAXN 100000
#define MAXE 1000000
#define DIMF 64

// Scratch (device globals; no allocation allowed)
__device__ float g_agg[MAXN * DIMF];
__device__ float g_h1[MAXN * DIMF];
__device__ float g_h2[MAXN * DIMF];
__device__ int   g_cnt[MAXN];
__device__ int   g_rowptr[MAXN + 1];
__device__ int   g_cursor[MAXN];
__device__ int2  g_edata[MAXE];          // {src, float_bits(w)} grouped by dst
__device__ int   g_bsum[512];

// ---------------------------------------------------------------------------
// CSR build: histogram -> exclusive scan -> fill
// ---------------------------------------------------------------------------
__global__ void zero_cnt_kernel(int* __restrict__ cnt, int N) {
    int i = blockIdx.x * blockDim.x + threadIdx.x;
    if (i < N) cnt[i] = 0;
}

__global__ void hist_kernel(const int* __restrict__ dst, int* __restrict__ cnt, int E) {
    int e = blockIdx.x * blockDim.x + threadIdx.x;
    if (e < E) atomicAdd(&cnt[dst[e]], 1);
}

__global__ void scan_partial_kernel(const int* __restrict__ cnt, int* __restrict__ bsum, int N) {
    __shared__ int sm[256];
    int i = blockIdx.x * 256 + threadIdx.x;
    sm[threadIdx.x] = (i < N) ? cnt[i] : 0;
    __syncthreads();
    for (int s = 128; s > 0; s >>= 1) {
        if (threadIdx.x < s) sm[threadIdx.x] += sm[threadIdx.x + s];
        __syncthreads();
    }
    if (threadIdx.x == 0) bsum[blockIdx.x] = sm[0];
}

__global__ void scan_top_kernel(int* __restrict__ bsum, int NB) {
    __shared__ int sm[512];
    int t = threadIdx.x;
    int v = (t < NB) ? bsum[t] : 0;
    sm[t] = v;
    __syncthreads();
    for (int s = 1; s < 512; s <<= 1) {
        int add = (t >= s) ? sm[t - s] : 0;
        __syncthreads();
        sm[t] += add;
        __syncthreads();
    }
    if (t < NB) bsum[t] = sm[t] - v;   // exclusive
}

__global__ void scan_final_kernel(const int* __restrict__ cnt,
                                  const int* __restrict__ bsum,
                                  int* __restrict__ rowptr,
                                  int* __restrict__ cursor, int N) {
    __shared__ int sm[256];
    int t = threadIdx.x;
    int i = blockIdx.x * 256 + t;
    int v = (i < N) ? cnt[i] : 0;
    sm[t] = v;
    __syncthreads();
    for (int s = 1; s < 256; s <<= 1) {
        int add = (t >= s) ? sm[t - s] : 0;
        __syncthreads();
        sm[t] += add;
        __syncthreads();
    }
    int val = bsum[blockIdx.x] + sm[t] - v;   // exclusive prefix
    if (i < N) {
        rowptr[i] = val;
        cursor[i] = val;
    } else if (i == N) {
        rowptr[N] = val;                      // == E
    }
}

__global__ void fill_kernel(const int* __restrict__ src, const int* __restrict__ dst,
                            const float* __restrict__ ew,
                            int* __restrict__ cursor, int2* __restrict__ edata, int E) {
    int e = blockIdx.x * blockDim.x + threadIdx.x;
    if (e >= E) return;
    int d = dst[e];
    int p = atomicAdd(&cursor[d], 1);
    edata[p] = make_int2(src[e], __float_as_int(ew[e]));
}

// ---------------------------------------------------------------------------
// Gather-aggregate: agg[n] = x[n] + sum_{e in csr(n)} x[src_e] * w_e
// 16 lanes per node. Per 16-edge chunk: each lane loads one edge's (src,w),
// broadcasts via shfl (width 16), then 16 independent coalesced x4 loads are
// issued back-to-back (MLP~16). Padding edges get w=0 -> no-op.
// ---------------------------------------------------------------------------
__global__ void gather_kernel(const float4* __restrict__ x4,
                              const int* __restrict__ rowptr,
                              const int2* __restrict__ edata,
                              float4* __restrict__ agg, int N) {
    int idx = blockIdx.x * blockDim.x + threadIdx.x;
    int n = idx >> 4;
    if (n >= N) return;
    int c = idx & 15;
    unsigned gmask = 0xFFFFu << (threadIdx.x & 16);   // this 16-lane group

    int beg = __ldg(rowptr + n);
    int end = __ldg(rowptr + n + 1);
    float4 acc = x4[(size_t)n * 16 + c];    // GIN identity term

    for (int base = beg; base < end; base += 16) {
        int e = base + c;
        int2 ed = (e < end) ? __ldg(edata + e) : make_int2(0, 0);
        #pragma unroll
        for (int i = 0; i < 16; i++) {
            int s   = __shfl_sync(gmask, ed.x, i, 16);
            float w = __int_as_float(__shfl_sync(gmask, ed.y, i, 16));
            float4 v = __ldg(&x4[(size_t)s * 16 + c]);
            acc.x += v.x * w; acc.y += v.y * w;
            acc.z += v.z * w; acc.w += v.w * w;
        }
    }
    agg[(size_t)n * 16 + c] = acc;
}

// ---------------------------------------------------------------------------
// Fused MLP: out = [relu]( relu(agg @ W1 + b1) @ W2 + b2 )   (unchanged R4)
// ---------------------------------------------------------------------------
template<int H, bool RELU_OUT>
__global__ void __launch_bounds__(256, 2) mlp_kernel(
        const float4* __restrict__ agg4,
        const float* __restrict__ w1, const float* __restrict__ b1,
        const float* __restrict__ w2, const float* __restrict__ b2,
        float4* __restrict__ out4, int N) {
    constexpr int TR  = 64;
    constexpr int INS = 65;
    constexpr int NP  = H / 64;

    extern __shared__ float sm[];
    float4* in_v = (float4*)sm;               // 16 * INS float4
    float*  w1t  = sm + 16 * INS * 4;         // H * 64
    float4* hid4 = (float4*)sm;               // reuses in_v+w1t region
    float*  w2t  = w1t + H * 64;              // 64 * H
    float*  b1s  = w2t + 64 * H;              // H
    float*  b2s  = b1s + H;                   // 64

    int tid  = threadIdx.x;
    int row0 = blockIdx.x * TR;
    int nrows = N - row0; if (nrows > TR) nrows = TR;

    for (int i = tid; i < 64 * H; i += 256) {
        int k = i / H, c = i % H;
        w1t[c * 64 + k] = w1[i];
    }
    for (int i = tid; i < H * 64; i += 256) {
        int h = i / 64, c = i % 64;
        w2t[c * H + h] = w2[i];
    }
    if (tid < H)  b1s[tid] = b1[tid];
    if (tid < 64) b2s[tid] = b2[tid];

    for (int i = tid; i < TR * 16; i += 256) {
        int r = i >> 4, k4 = i & 15;
        float4 v = make_float4(0.f, 0.f, 0.f, 0.f);
        if (r < nrows) v = agg4[(size_t)(row0 + r) * 16 + k4];
        in_v[k4 * INS + r] = v;
    }
    __syncthreads();

    const int rg = tid & 15;
    const int cg = tid >> 4;

    float acc1[NP][4][4];
    #pragma unroll
    for (int p = 0; p < NP; p++) {
        int c0 = (p * 16 + cg) * 4;
        #pragma unroll
        for (int j = 0; j < 4; j++) {
            acc1[p][j][0] = b1s[c0];     acc1[p][j][1] = b1s[c0 + 1];
            acc1[p][j][2] = b1s[c0 + 2]; acc1[p][j][3] = b1s[c0 + 3];
        }
    }
    #pragma unroll
    for (int k4 = 0; k4 < 16; ++k4) {
        float4 iv[4];
        #pragma unroll
        for (int j = 0; j < 4; j++) iv[j] = in_v[k4 * INS + rg + 16 * j];
        #pragma unroll
        for (int p = 0; p < NP; p++) {
            int c0 = (p * 16 + cg) * 4;
            float4 wv0 = *(const float4*)(w1t + (c0 + 0) * 64 + k4 * 4);
            float4 wv1 = *(const float4*)(w1t + (c0 + 1) * 64 + k4 * 4);
            float4 wv2 = *(const float4*)(w1t + (c0 + 2) * 64 + k4 * 4);
            float4 wv3 = *(const float4*)(w1t + (c0 + 3) * 64 + k4 * 4);
            #pragma unroll
            for (int j = 0; j < 4; j++) {
                acc1[p][j][0] += iv[j].x * wv0.x + iv[j].y * wv0.y + iv[j].z * wv0.z + iv[j].w * wv0.w;
                acc1[p][j][1] += iv[j].x * wv1.x + iv[j].y * wv1.y + iv[j].z * wv1.z + iv[j].w * wv1.w;
                acc1[p][j][2] += iv[j].x * wv2.x + iv[j].y * wv2.y + iv[j].z * wv2.z + iv[j].w * wv2.w;
                acc1[p][j][3] += iv[j].x * wv3.x + iv[j].y * wv3.y + iv[j].z * wv3.z + iv[j].w * wv3.w;
            }
        }
    }
    __syncthreads();

    #pragma unroll
    for (int p = 0; p < NP; p++) {
        #pragma unroll
        for (int j = 0; j < 4; j++) {
            hid4[(p * 16 + cg) * 64 + rg + 16 * j] = make_float4(
                fmaxf(acc1[p][j][0], 0.f), fmaxf(acc1[p][j][1], 0.f),
                fmaxf(acc1[p][j][2], 0.f), fmaxf(acc1[p][j][3], 0.f));
        }
    }
    __syncthreads();

    {
        int c0 = cg * 4;
        float acc[4][4];
        #pragma unroll
        for (int j = 0; j < 4; j++) {
            acc[j][0] = b2s[c0];     acc[j][1] = b2s[c0 + 1];
            acc[j][2] = b2s[c0 + 2]; acc[j][3] = b2s[c0 + 3];
        }
        #pragma unroll
        for (int h4 = 0; h4 < H / 4; ++h4) {
            float4 hv[4];
            #pragma unroll
            for (int j = 0; j < 4; j++) hv[j] = hid4[h4 * 64 + rg + 16 * j];
            float4 wv0 = *(const float4*)(w2t + (c0 + 0) * H + h4 * 4);
            float4 wv1 = *(const float4*)(w2t + (c0 + 1) * H + h4 * 4);
            float4 wv2 = *(const float4*)(w2t + (c0 + 2) * H + h4 * 4);
            float4 wv3 = *(const float4*)(w2t + (c0 + 3) * H + h4 * 4);
            #pragma unroll
            for (int j = 0; j < 4; j++) {
                acc[j][0] += hv[j].x * wv0.x + hv[j].y * wv0.y + hv[j].z * wv0.z + hv[j].w * wv0.w;
                acc[j][1] += hv[j].x * wv1.x + hv[j].y * wv1.y + hv[j].z * wv1.z + hv[j].w * wv1.w;
                acc[j][2] += hv[j].x * wv2.x + hv[j].y * wv2.y + hv[j].z * wv2.z + hv[j].w * wv2.w;
                acc[j][3] += hv[j].x * wv3.x + hv[j].y * wv3.y + hv[j].z * wv3.z + hv[j].w * wv3.w;
            }
        }
        #pragma unroll
        for (int j = 0; j < 4; j++) {
            int r = rg + 16 * j;
            if (r < nrows) {
                float4 v;
                if (RELU_OUT) {
                    v = make_float4(fmaxf(acc[j][0], 0.f), fmaxf(acc[j][1], 0.f),
                                    fmaxf(acc[j][2], 0.f), fmaxf(acc[j][3], 0.f));
                } else {
                    v = make_float4(acc[j][0], acc[j][1], acc[j][2], acc[j][3]);
                }
                out4[(size_t)(row0 + r) * 16 + cg] = v;
            }
        }
    }
}

// ---------------------------------------------------------------------------
// Launch
// ---------------------------------------------------------------------------
static inline size_t mlp_smem(int H) {
    size_t region0 = 16 * 65 * 4 + (size_t)H * 64;  // in_v + w1t (>= hid)
    return (region0 + 64 * H + H + 64) * sizeof(float);
}

extern "C" void kernel_launch(void* const* d_in, const int* in_sizes, int n_in,
                              void* d_out, int out_size) {
    const float* x   = (const float*)d_in[0];
    const int*   ei  = (const int*)d_in[1];
    const float* ew  = (const float*)d_in[2];
    const float* w11 = (const float*)d_in[3];
    const float* b11 = (const float*)d_in[4];
    const float* w12 = (const float*)d_in[5];
    const float* b12 = (const float*)d_in[6];
    const float* w21 = (const float*)d_in[7];
    const float* b21 = (const float*)d_in[8];
    const float* w22 = (const float*)d_in[9];
    const float* b22 = (const float*)d_in[10];
    const float* w31 = (const float*)d_in[11];
    const float* b31 = (const float*)d_in[12];
    const float* w32 = (const float*)d_in[13];
    const float* b32 = (const float*)d_in[14];
    float* out = (float*)d_out;

    int N = in_sizes[0] / DIMF;
    int E = in_sizes[1] / 2;
    const int* src = ei;
    const int* dst = ei + E;

    float *agg, *h1, *h2;
    int *cnt, *rowptr, *cursor, *bsum;
    int2 *edata;
    cudaGetSymbolAddress((void**)&agg, g_agg);
    cudaGetSymbolAddress((void**)&h1, g_h1);
    cudaGetSymbolAddress((void**)&h2, g_h2);
    cudaGetSymbolAddress((void**)&cnt, g_cnt);
    cudaGetSymbolAddress((void**)&rowptr, g_rowptr);
    cudaGetSymbolAddress((void**)&cursor, g_cursor);
    cudaGetSymbolAddress((void**)&bsum, g_bsum);
    cudaGetSymbolAddress((void**)&edata, g_edata);

    size_t sm64  = mlp_smem(64);
    size_t sm128 = mlp_smem(128);
    cudaFuncSetAttribute(mlp_kernel<64, true>,  cudaFuncAttributeMaxDynamicSharedMemorySize, (int)sm64);
    cudaFuncSetAttribute(mlp_kernel<128, true>, cudaFuncAttributeMaxDynamicSharedMemorySize, (int)sm128);
    cudaFuncSetAttribute(mlp_kernel<64, false>, cudaFuncAttributeMaxDynamicSharedMemorySize, (int)sm64);

    int NB = (N + 255) / 256;                // scan blocks (<=512 required)
    int eb = (E + 255) / 256;
    int gb = (N * 16 + 255) / 256;
    int mb = (N + 63) / 64;

    // --- CSR build (by destination) ---
    zero_cnt_kernel<<<NB, 256>>>(cnt, N);
    hist_kernel<<<eb, 256>>>(dst, cnt, E);
    scan_partial_kernel<<<NB, 256>>>(cnt, bsum, N);
    scan_top_kernel<<<1, 512>>>(bsum, NB);
    scan_final_kernel<<<NB + 1, 256>>>(cnt, bsum, rowptr, cursor, N);
    fill_kernel<<<eb, 256>>>(src, dst, ew, cursor, edata, E);

    // --- Layer 1: 64 -> 64 -> 64, relu ---
    gather_kernel<<<gb, 256>>>((const float4*)x, rowptr, edata, (float4*)agg, N);
    mlp_kernel<64, true><<<mb, 256, sm64>>>((const float4*)agg, w11, b11, w12, b12, (float4*)h1, N);

    // --- Layer 2: 64 -> 128 -> 64, relu ---
    gather_kernel<<<gb, 256>>>((const float4*)h1, rowptr, edata, (float4*)agg, N);
    mlp_kernel<128, true><<<mb, 256, sm128>>>((const float4*)agg, w21, b21, w22, b22, (float4*)h2, N);

    // --- Layer 3: 64 -> 64 -> 64, no relu ---
    gather_kernel<<<gb, 256>>>((const float4*)h2, rowptr, edata, (float4*)agg, N);
    mlp_kernel<64, false><<<mb, 256, sm64>>>((const float4*)agg, w31, b31, w32, b32, (float4*)out, N);
}

// round 7
// speedup vs baseline: 2.2843x; 1.4749x over previous
#include <cuda_runtime.h>
#include <cuda_bf16.h>

// Problem constants (reference: N=100000, E=1000000, D=64)
#define MAXN 100000
#define MAXE 1000000
#define DIMF 64

// Scratch (device globals; no allocation allowed)
__device__ float g_agg[MAXN * DIMF];
__device__ float g_h1[MAXN * DIMF];
__device__ float g_h2[MAXN * DIMF];
__device__ int   g_cnt[MAXN];
__device__ int   g_rowptr[MAXN + 1];
__device__ int   g_cursor[MAXN];
__device__ int2  g_edata[MAXE];          // {src, float_bits(w)} grouped by dst
__device__ int   g_bsum[512];

// ---------------------------------------------------------------------------
// CSR build: histogram -> exclusive scan -> fill
// ---------------------------------------------------------------------------
__global__ void zero_cnt_kernel(int* __restrict__ cnt, int N) {
    int i = blockIdx.x * blockDim.x + threadIdx.x;
    if (i < N) cnt[i] = 0;
}

__global__ void hist_kernel(const int* __restrict__ dst, int* __restrict__ cnt, int E) {
    int e = blockIdx.x * blockDim.x + threadIdx.x;
    if (e < E) atomicAdd(&cnt[dst[e]], 1);
}

__global__ void scan_partial_kernel(const int* __restrict__ cnt, int* __restrict__ bsum, int N) {
    __shared__ int sm[256];
    int i = blockIdx.x * 256 + threadIdx.x;
    sm[threadIdx.x] = (i < N) ? cnt[i] : 0;
    __syncthreads();
    for (int s = 128; s > 0; s >>= 1) {
        if (threadIdx.x < s) sm[threadIdx.x] += sm[threadIdx.x + s];
        __syncthreads();
    }
    if (threadIdx.x == 0) bsum[blockIdx.x] = sm[0];
}

__global__ void scan_top_kernel(int* __restrict__ bsum, int NB) {
    __shared__ int sm[512];
    int t = threadIdx.x;
    int v = (t < NB) ? bsum[t] : 0;
    sm[t] = v;
    __syncthreads();
    for (int s = 1; s < 512; s <<= 1) {
        int add = (t >= s) ? sm[t - s] : 0;
        __syncthreads();
        sm[t] += add;
        __syncthreads();
    }
    if (t < NB) bsum[t] = sm[t] - v;   // exclusive
}

__global__ void scan_final_kernel(const int* __restrict__ cnt,
                                  const int* __restrict__ bsum,
                                  int* __restrict__ rowptr,
                                  int* __restrict__ cursor, int N) {
    __shared__ int sm[256];
    int t = threadIdx.x;
    int i = blockIdx.x * 256 + t;
    int v = (i < N) ? cnt[i] : 0;
    sm[t] = v;
    __syncthreads();
    for (int s = 1; s < 256; s <<= 1) {
        int add = (t >= s) ? sm[t - s] : 0;
        __syncthreads();
        sm[t] += add;
        __syncthreads();
    }
    int val = bsum[blockIdx.x] + sm[t] - v;   // exclusive prefix
    if (i < N) {
        rowptr[i] = val;
        cursor[i] = val;
    } else if (i == N) {
        rowptr[N] = val;                      // == E
    }
}

__global__ void fill_kernel(const int* __restrict__ src, const int* __restrict__ dst,
                            const float* __restrict__ ew,
                            int* __restrict__ cursor, int2* __restrict__ edata, int E) {
    int e = blockIdx.x * blockDim.x + threadIdx.x;
    if (e >= E) return;
    int d = dst[e];
    int p = atomicAdd(&cursor[d], 1);
    edata[p] = make_int2(src[e], __float_as_int(ew[e]));
}

// ---------------------------------------------------------------------------
// Gather-aggregate: agg[n] = x[n] + sum_{e in csr(n)} x[src_e] * w_e
// (unchanged R6: 16 lanes/node, shfl-distributed edges, MLP~16)
// ---------------------------------------------------------------------------
__global__ void gather_kernel(const float4* __restrict__ x4,
                              const int* __restrict__ rowptr,
                              const int2* __restrict__ edata,
                              float4* __restrict__ agg, int N) {
    int idx = blockIdx.x * blockDim.x + threadIdx.x;
    int n = idx >> 4;
    if (n >= N) return;
    int c = idx & 15;
    unsigned gmask = 0xFFFFu << (threadIdx.x & 16);   // this 16-lane group

    int beg = __ldg(rowptr + n);
    int end = __ldg(rowptr + n + 1);
    float4 acc = x4[(size_t)n * 16 + c];    // GIN identity term

    for (int base = beg; base < end; base += 16) {
        int e = base + c;
        int2 ed = (e < end) ? __ldg(edata + e) : make_int2(0, 0);
        #pragma unroll
        for (int i = 0; i < 16; i++) {
            int s   = __shfl_sync(gmask, ed.x, i, 16);
            float w = __int_as_float(__shfl_sync(gmask, ed.y, i, 16));
            float4 v = __ldg(&x4[(size_t)s * 16 + c]);
            acc.x += v.x * w; acc.y += v.y * w;
            acc.z += v.z * w; acc.w += v.w * w;
        }
    }
    agg[(size_t)n * 16 + c] = acc;
}

// ---------------------------------------------------------------------------
// Fused MLP: out = [relu]( relu(agg @ W1 + b1) @ W2 + b2 )
//
// Weights stay in NATURAL row-major layout in smem (straight float4 copy,
// conflict-free) -- reads are broadcast within each 16-lane group so layout
// does not matter for the GEMM. Inner loop: per k, broadcast-load
// w[k][c0..c0+3] as float4; per-row scalars come from the staged transposed
// input in_v[k4][r] (float4 of 4 consecutive k). This removes the 32-way
// bank-conflicted weight-transpose stores of the previous version.
// ---------------------------------------------------------------------------
template<int H, bool RELU_OUT>
__global__ void __launch_bounds__(256, 2) mlp_kernel(
        const float4* __restrict__ agg4,
        const float4* __restrict__ w1, const float* __restrict__ b1,
        const float4* __restrict__ w2, const float* __restrict__ b2,
        float4* __restrict__ out4, int N) {
    constexpr int TR  = 64;
    constexpr int INS = 65;
    constexpr int NP  = H / 64;

    extern __shared__ float sm[];
    float4* in_v = (float4*)sm;               // 16 * INS float4
    float*  w1n  = sm + 16 * INS * 4;         // 64 * H   natural: w1n[k*H+c]
    float4* hid4 = (float4*)sm;               // reuses in_v+w1n region
    float*  w2n  = w1n + 64 * H;              // H * 64   natural: w2n[h*64+c]
    float*  b1s  = w2n + H * 64;              // H
    float*  b2s  = b1s + H;                   // 64

    int tid  = threadIdx.x;
    int row0 = blockIdx.x * TR;
    int nrows = N - row0; if (nrows > TR) nrows = TR;

    // Conflict-free, coalesced weight copies (natural layout)
    for (int i = tid; i < 64 * H / 4; i += 256)
        ((float4*)w1n)[i] = w1[i];
    for (int i = tid; i < H * 64 / 4; i += 256)
        ((float4*)w2n)[i] = w2[i];
    if (tid < H)  b1s[tid] = b1[tid];
    if (tid < 64) b2s[tid] = b2[tid];

    for (int i = tid; i < TR * 16; i += 256) {
        int r = i >> 4, k4 = i & 15;
        float4 v = make_float4(0.f, 0.f, 0.f, 0.f);
        if (r < nrows) v = agg4[(size_t)(row0 + r) * 16 + k4];
        in_v[k4 * INS + r] = v;
    }
    __syncthreads();

    const int rg = tid & 15;   // rows rg + 16j
    const int cg = tid >> 4;   // col group (uniform per half-warp -> broadcast)

    // GEMM1: acc1 = in @ W1 + b1, kept in registers
    float acc1[NP][4][4];
    #pragma unroll
    for (int p = 0; p < NP; p++) {
        int c0 = (p * 16 + cg) * 4;
        #pragma unroll
        for (int j = 0; j < 4; j++) {
            acc1[p][j][0] = b1s[c0];     acc1[p][j][1] = b1s[c0 + 1];
            acc1[p][j][2] = b1s[c0 + 2]; acc1[p][j][3] = b1s[c0 + 3];
        }
    }
    #pragma unroll
    for (int k4 = 0; k4 < 16; ++k4) {
        float4 iv[4];
        #pragma unroll
        for (int j = 0; j < 4; j++) iv[j] = in_v[k4 * INS + rg + 16 * j];
        #pragma unroll
        for (int p = 0; p < NP; p++) {
            int c0 = (p * 16 + cg) * 4;
            // 4 broadcast float4 loads: rows k4*4..k4*4+3, cols c0..c0+3
            float4 wv0 = *(const float4*)(w1n + (k4 * 4 + 0) * H + c0);
            float4 wv1 = *(const float4*)(w1n + (k4 * 4 + 1) * H + c0);
            float4 wv2 = *(const float4*)(w1n + (k4 * 4 + 2) * H + c0);
            float4 wv3 = *(const float4*)(w1n + (k4 * 4 + 3) * H + c0);
            #pragma unroll
            for (int j = 0; j < 4; j++) {
                acc1[p][j][0] += iv[j].x * wv0.x + iv[j].y * wv1.x + iv[j].z * wv2.x + iv[j].w * wv3.x;
                acc1[p][j][1] += iv[j].x * wv0.y + iv[j].y * wv1.y + iv[j].z * wv2.y + iv[j].w * wv3.y;
                acc1[p][j][2] += iv[j].x * wv0.z + iv[j].y * wv1.z + iv[j].z * wv2.z + iv[j].w * wv3.z;
                acc1[p][j][3] += iv[j].x * wv0.w + iv[j].y * wv1.w + iv[j].z * wv2.w + iv[j].w * wv3.w;
            }
        }
    }
    __syncthreads();   // all reads of in_v / w1n complete

    // Store relu(hid) k-major: hid4[h4][r]  (reuses in_v+w1n region)
    #pragma unroll
    for (int p = 0; p < NP; p++) {
        #pragma unroll
        for (int j = 0; j < 4; j++) {
            hid4[(p * 16 + cg) * 64 + rg + 16 * j] = make_float4(
                fmaxf(acc1[p][j][0], 0.f), fmaxf(acc1[p][j][1], 0.f),
                fmaxf(acc1[p][j][2], 0.f), fmaxf(acc1[p][j][3], 0.f));
        }
    }
    __syncthreads();

    // GEMM2: out = hid @ W2 + b2
    {
        int c0 = cg * 4;
        float acc[4][4];
        #pragma unroll
        for (int j = 0; j < 4; j++) {
            acc[j][0] = b2s[c0];     acc[j][1] = b2s[c0 + 1];
            acc[j][2] = b2s[c0 + 2]; acc[j][3] = b2s[c0 + 3];
        }
        #pragma unroll
        for (int h4 = 0; h4 < H / 4; ++h4) {
            float4 hv[4];
            #pragma unroll
            for (int j = 0; j < 4; j++) hv[j] = hid4[h4 * 64 + rg + 16 * j];
            float4 wv0 = *(const float4*)(w2n + (h4 * 4 + 0) * 64 + c0);
            float4 wv1 = *(const float4*)(w2n + (h4 * 4 + 1) * 64 + c0);
            float4 wv2 = *(const float4*)(w2n + (h4 * 4 + 2) * 64 + c0);
            float4 wv3 = *(const float4*)(w2n + (h4 * 4 + 3) * 64 + c0);
            #pragma unroll
            for (int j = 0; j < 4; j++) {
                acc[j][0] += hv[j].x * wv0.x + hv[j].y * wv1.x + hv[j].z * wv2.x + hv[j].w * wv3.x;
                acc[j][1] += hv[j].x * wv0.y + hv[j].y * wv1.y + hv[j].z * wv2.y + hv[j].w * wv3.y;
                acc[j][2] += hv[j].x * wv0.z + hv[j].y * wv1.z + hv[j].z * wv2.z + hv[j].w * wv3.z;
                acc[j][3] += hv[j].x * wv0.w + hv[j].y * wv1.w + hv[j].z * wv2.w + hv[j].w * wv3.w;
            }
        }
        #pragma unroll
        for (int j = 0; j < 4; j++) {
            int r = rg + 16 * j;
            if (r < nrows) {
                float4 v;
                if (RELU_OUT) {
                    v = make_float4(fmaxf(acc[j][0], 0.f), fmaxf(acc[j][1], 0.f),
                                    fmaxf(acc[j][2], 0.f), fmaxf(acc[j][3], 0.f));
                } else {
                    v = make_float4(acc[j][0], acc[j][1], acc[j][2], acc[j][3]);
                }
                out4[(size_t)(row0 + r) * 16 + cg] = v;
            }
        }
    }
}

// ---------------------------------------------------------------------------
// Launch
// ---------------------------------------------------------------------------
static inline size_t mlp_smem(int H) {
    size_t region0 = 16 * 65 * 4 + (size_t)64 * H;  // in_v + w1n (>= hid)
    return (region0 + (size_t)H * 64 + H + 64) * sizeof(float);
}

extern "C" void kernel_launch(void* const* d_in, const int* in_sizes, int n_in,
                              void* d_out, int out_size) {
    const float* x   = (const float*)d_in[0];
    const int*   ei  = (const int*)d_in[1];
    const float* ew  = (const float*)d_in[2];
    const float* w11 = (const float*)d_in[3];
    const float* b11 = (const float*)d_in[4];
    const float* w12 = (const float*)d_in[5];
    const float* b12 = (const float*)d_in[6];
    const float* w21 = (const float*)d_in[7];
    const float* b21 = (const float*)d_in[8];
    const float* w22 = (const float*)d_in[9];
    const float* b22 = (const float*)d_in[10];
    const float* w31 = (const float*)d_in[11];
    const float* b31 = (const float*)d_in[12];
    const float* w32 = (const float*)d_in[13];
    const float* b32 = (const float*)d_in[14];
    float* out = (float*)d_out;

    int N = in_sizes[0] / DIMF;
    int E = in_sizes[1] / 2;
    const int* src = ei;
    const int* dst = ei + E;

    float *agg, *h1, *h2;
    int *cnt, *rowptr, *cursor, *bsum;
    int2 *edata;
    cudaGetSymbolAddress((void**)&agg, g_agg);
    cudaGetSymbolAddress((void**)&h1, g_h1);
    cudaGetSymbolAddress((void**)&h2, g_h2);
    cudaGetSymbolAddress((void**)&cnt, g_cnt);
    cudaGetSymbolAddress((void**)&rowptr, g_rowptr);
    cudaGetSymbolAddress((void**)&cursor, g_cursor);
    cudaGetSymbolAddress((void**)&bsum, g_bsum);
    cudaGetSymbolAddress((void**)&edata, g_edata);

    size_t sm64  = mlp_smem(64);
    size_t sm128 = mlp_smem(128);
    cudaFuncSetAttribute(mlp_kernel<64, true>,  cudaFuncAttributeMaxDynamicSharedMemorySize, (int)sm64);
    cudaFuncSetAttribute(mlp_kernel<128, true>, cudaFuncAttributeMaxDynamicSharedMemorySize, (int)sm128);
    cudaFuncSetAttribute(mlp_kernel<64, false>, cudaFuncAttributeMaxDynamicSharedMemorySize, (int)sm64);

    int NB = (N + 255) / 256;                // scan blocks (<=512 required)
    int eb = (E + 255) / 256;
    int gb = (N * 16 + 255) / 256;
    int mb = (N + 63) / 64;

    // --- CSR build (by destination) ---
    zero_cnt_kernel<<<NB, 256>>>(cnt, N);
    hist_kernel<<<eb, 256>>>(dst, cnt, E);
    scan_partial_kernel<<<NB, 256>>>(cnt, bsum, N);
    scan_top_kernel<<<1, 512>>>(bsum, NB);
    scan_final_kernel<<<NB + 1, 256>>>(cnt, bsum, rowptr, cursor, N);
    fill_kernel<<<eb, 256>>>(src, dst, ew, cursor, edata, E);

    // --- Layer 1: 64 -> 64 -> 64, relu ---
    gather_kernel<<<gb, 256>>>((const float4*)x, rowptr, edata, (float4*)agg, N);
    mlp_kernel<64, true><<<mb, 256, sm64>>>((const float4*)agg,
        (const float4*)w11, b11, (const float4*)w12, b12, (float4*)h1, N);

    // --- Layer 2: 64 -> 128 -> 64, relu ---
    gather_kernel<<<gb, 256>>>((const float4*)h1, rowptr, edata, (float4*)agg, N);
    mlp_kernel<128, true><<<mb, 256, sm128>>>((const float4*)agg,
        (const float4*)w21, b21, (const float4*)w22, b22, (float4*)h2, N);

    // --- Layer 3: 64 -> 64 -> 64, no relu ---
    gather_kernel<<<gb, 256>>>((const float4*)h2, rowptr, edata, (float4*)agg, N);
    mlp_kernel<64, false><<<mb, 256, sm64>>>((const float4*)agg,
        (const float4*)w31, b31, (const float4*)w32, b32, (float4*)out, N);
}